// round 16
// baseline (speedup 1.0000x reference)
#include <cuda_runtime.h>
#include <math.h>

#define BB 32
#define TT 1024
#define DD 512
#define KK 64
#define OO 1024
#define KD (KK * DD)
#define F_EPS 1e-12f

typedef unsigned long long ull;

__device__ __forceinline__ float tf32_rna(float v) {
    float h; asm("cvt.rna.tf32.f32 %0, %1;" : "=f"(h) : "f"(v)); return h;
}
__device__ __forceinline__ void red2(float* p, float a, float b) {
    asm volatile("red.global.add.v2.f32 [%0], {%1, %2};"
                 :: "l"(p), "f"(a), "f"(b) : "memory");
}
__device__ __forceinline__ void cp16cg(void* s, const void* g) {
    unsigned a = (unsigned)__cvta_generic_to_shared(s);
    asm volatile("cp.async.cg.shared.global [%0], [%1], 16;" :: "r"(a), "l"(g) : "memory");
}
__device__ __forceinline__ void cp16ca(void* s, const void* g) {
    unsigned a = (unsigned)__cvta_generic_to_shared(s);
    asm volatile("cp.async.ca.shared.global [%0], [%1], 16;" :: "r"(a), "l"(g) : "memory");
}
#define CP_COMMIT() asm volatile("cp.async.commit_group;" ::: "memory")
#define CP_WAIT2()  asm volatile("cp.async.wait_group 2;" ::: "memory")
#define CP_WAIT1()  asm volatile("cp.async.wait_group 1;" ::: "memory")
#define CP_WAIT0()  asm volatile("cp.async.wait_group 0;" ::: "memory")

#define MMA8(Cp, a0, a1, a2, a3, b0, b1)                                        \
    asm volatile(                                                               \
        "mma.sync.aligned.m16n8k8.row.col.f32.tf32.tf32.f32 "                   \
        "{%0,%1,%2,%3}, {%4,%5,%6,%7}, {%8,%9}, {%0,%1,%2,%3};"                 \
        : "+f"((Cp)[0]), "+f"((Cp)[1]), "+f"((Cp)[2]), "+f"((Cp)[3])            \
        : "r"(a0), "r"(a1), "r"(a2), "r"(a3), "r"(b0), "r"(b1))

__device__ float g_a[BB * TT * KK];
__device__ float g_agg[BB * KK * DD];
__device__ float g_v64[64 * KD];     // rows 0-31: tf32-hi(v); rows 32-63: residual
__device__ float g_sumw[BB * KK];
__device__ float g_norm2[BB];

// ---------------------------------------------------------------------------
// K1: logits -> softmax -> a, sum_w. 256 threads / 8 warps (2 per SMSP).
// Warp w owns rows r0 + w*16 .. +16 (one m16 tile), all 64 k.
// ---------------------------------------------------------------------------
__global__ __launch_bounds__(256) void k_assign_mma(const float* __restrict__ x,
                                                    const float* __restrict__ w,
                                                    const float* __restrict__ bias) {
    __shared__ __align__(16) float sX[128 * 36];
    __shared__ __align__(16) float sWh[32 * 72];
    __shared__ __align__(16) float sWl[32 * 72];
    __shared__ float bias_s[64];
    __shared__ float ssum[64];

    const int tid = threadIdx.x;
    const int lane = tid & 31, warp = tid >> 5;
    const int grp = lane >> 2, qid = lane & 3;
    const int r0 = blockIdx.x * 128;
    const int b = r0 >> 10;

    if (tid < 64) { ssum[tid] = 0.0f; bias_s[tid] = bias[tid]; }

    float C[8][4];
#pragma unroll
    for (int j = 0; j < 8; j++)
#pragma unroll
        for (int q = 0; q < 4; q++) C[j][q] = 0.0f;

    float4 pX[4], pW[2];

#define K1_LDG(c0)                                                              \
    do {                                                                        \
        _Pragma("unroll")                                                       \
        for (int i_ = 0; i_ < 4; i_++) {                                        \
            int idx = tid + i_ * 256;                                           \
            pX[i_] = *(const float4*)&x[(size_t)(r0 + (idx >> 3)) * DD + (c0)   \
                                        + (idx & 7) * 4];                       \
        }                                                                       \
        _Pragma("unroll")                                                       \
        for (int i_ = 0; i_ < 2; i_++) {                                        \
            int idx = tid + i_ * 256;                                           \
            pW[i_] = *(const float4*)&w[(size_t)((c0) + (idx >> 4)) * KK        \
                                        + (idx & 15) * 4];                      \
        }                                                                       \
    } while (0)
#define K1_STS()                                                                \
    do {                                                                        \
        _Pragma("unroll")                                                       \
        for (int i_ = 0; i_ < 4; i_++) {                                        \
            int idx = tid + i_ * 256;                                           \
            *(float4*)&sX[(idx >> 3) * 36 + (idx & 7) * 4] = pX[i_];            \
        }                                                                       \
        _Pragma("unroll")                                                       \
        for (int i_ = 0; i_ < 2; i_++) {                                        \
            int idx = tid + i_ * 256;                                           \
            float4 h_, l_;                                                      \
            h_.x = tf32_rna(pW[i_].x); l_.x = pW[i_].x - h_.x;                  \
            h_.y = tf32_rna(pW[i_].y); l_.y = pW[i_].y - h_.y;                  \
            h_.z = tf32_rna(pW[i_].z); l_.z = pW[i_].z - h_.z;                  \
            h_.w = tf32_rna(pW[i_].w); l_.w = pW[i_].w - h_.w;                  \
            *(float4*)&sWh[(idx >> 4) * 72 + (idx & 15) * 4] = h_;              \
            *(float4*)&sWl[(idx >> 4) * 72 + (idx & 15) * 4] = l_;              \
        }                                                                       \
    } while (0)

    K1_LDG(0);
    K1_STS();
    __syncthreads();

    const int NC = DD / 32;   // 16
    for (int c = 0; c < NC; c++) {
        if (c + 1 < NC) K1_LDG((c + 1) * 32);

#pragma unroll
        for (int ks = 0; ks < 4; ks++) {
            const int k0 = ks * 8;
            const int base = warp * 16;
            unsigned ah[4], al[4];
            {
                float v0 = sX[(base + grp) * 36 + k0 + qid];
                float v1 = sX[(base + grp + 8) * 36 + k0 + qid];
                float v2 = sX[(base + grp) * 36 + k0 + qid + 4];
                float v3 = sX[(base + grp + 8) * 36 + k0 + qid + 4];
                float h0 = tf32_rna(v0), h1 = tf32_rna(v1);
                float h2 = tf32_rna(v2), h3 = tf32_rna(v3);
                ah[0] = __float_as_uint(h0); al[0] = __float_as_uint(v0 - h0);
                ah[1] = __float_as_uint(h1); al[1] = __float_as_uint(v1 - h1);
                ah[2] = __float_as_uint(h2); al[2] = __float_as_uint(v2 - h2);
                ah[3] = __float_as_uint(h3); al[3] = __float_as_uint(v3 - h3);
            }
#pragma unroll
            for (int j = 0; j < 8; j++) {
                const int n = j * 8 + grp;
                unsigned bh0 = __float_as_uint(sWh[(k0 + qid) * 72 + n]);
                unsigned bh1 = __float_as_uint(sWh[(k0 + qid + 4) * 72 + n]);
                unsigned bl0 = __float_as_uint(sWl[(k0 + qid) * 72 + n]);
                unsigned bl1 = __float_as_uint(sWl[(k0 + qid + 4) * 72 + n]);
                MMA8(C[j], ah[0], ah[1], ah[2], ah[3], bh0, bh1);
                MMA8(C[j], ah[0], ah[1], ah[2], ah[3], bl0, bl1);
                MMA8(C[j], al[0], al[1], al[2], al[3], bh0, bh1);
            }
        }
        __syncthreads();
        if (c + 1 < NC) {
            K1_STS();
            __syncthreads();
        }
    }
#undef K1_LDG
#undef K1_STS

    float cs[8][2];
#pragma unroll
    for (int j = 0; j < 8; j++) { cs[j][0] = 0.0f; cs[j][1] = 0.0f; }

#pragma unroll
    for (int s = 0; s < 2; s++) {
        float va[8], vb[8];
        float m = -1e30f;
#pragma unroll
        for (int j = 0; j < 8; j++) {
            va[j] = C[j][s * 2 + 0] + bias_s[j * 8 + qid * 2];
            vb[j] = C[j][s * 2 + 1] + bias_s[j * 8 + qid * 2 + 1];
            m = fmaxf(m, fmaxf(va[j], vb[j]));
        }
        m = fmaxf(m, __shfl_xor_sync(0xffffffffu, m, 1));
        m = fmaxf(m, __shfl_xor_sync(0xffffffffu, m, 2));
        float sm = 0.0f;
#pragma unroll
        for (int j = 0; j < 8; j++) {
            va[j] = __expf(va[j] - m);
            vb[j] = __expf(vb[j] - m);
            sm += va[j] + vb[j];
        }
        sm += __shfl_xor_sync(0xffffffffu, sm, 1);
        sm += __shfl_xor_sync(0xffffffffu, sm, 2);
        float inv = 1.0f / sm;
        const int row = r0 + warp * 16 + s * 8 + grp;
#pragma unroll
        for (int j = 0; j < 8; j++) {
            float2 o;
            o.x = va[j] * inv; o.y = vb[j] * inv;
            *(float2*)&g_a[(size_t)row * KK + j * 8 + qid * 2] = o;
            cs[j][0] += o.x; cs[j][1] += o.y;
        }
    }
#pragma unroll
    for (int j = 0; j < 8; j++) {
#pragma unroll
        for (int off = 4; off < 32; off <<= 1) {
            cs[j][0] += __shfl_xor_sync(0xffffffffu, cs[j][0], off);
            cs[j][1] += __shfl_xor_sync(0xffffffffu, cs[j][1], off);
        }
    }
    if (grp == 0) {
#pragma unroll
        for (int j = 0; j < 8; j++) {
            atomicAdd(&ssum[j * 8 + qid * 2], cs[j][0]);
            atomicAdd(&ssum[j * 8 + qid * 2 + 1], cs[j][1]);
        }
    }
    __syncthreads();
    if (tid < 64) atomicAdd(&g_sumw[b * KK + tid], ssum[tid]);
}

// ---------------------------------------------------------------------------
// K2: x_agg = a^T x. 256 threads / 8 warps. Warp w: m-half (w>>2), n (w&3)*32.
// One block per (b, dtile) -> plain stores. grid 128, NC=32 chunks of 32 t.
// ---------------------------------------------------------------------------
__global__ __launch_bounds__(256) void k_agg_mma(const float* __restrict__ x) {
    __shared__ __align__(16) float sAh[32 * 72];
    __shared__ __align__(16) float sAl[32 * 72];
    __shared__ __align__(16) float sX2[32 * 136];

    const int tid = threadIdx.x;
    const int lane = tid & 31, warp = tid >> 5;
    const int grp = lane >> 2, qid = lane & 3;
    const int bx = blockIdx.x;
    const int b  = bx >> 2;
    const int dt = bx & 3;
    const int nb  = (warp & 3) * 32;
    const int mh2 = (warp >> 2) * 2;     // mt in {mh2, mh2+1}

    float C[2][4][4];
#pragma unroll
    for (int mt = 0; mt < 2; mt++)
#pragma unroll
        for (int j = 0; j < 4; j++)
#pragma unroll
            for (int q = 0; q < 4; q++) C[mt][j][q] = 0.0f;

    float4 pA[2], pX[4];

#define K2_LDG(tc)                                                              \
    do {                                                                        \
        _Pragma("unroll")                                                       \
        for (int i_ = 0; i_ < 2; i_++) {                                        \
            int idx = tid + i_ * 256;                                           \
            pA[i_] = *(const float4*)&g_a[(size_t)(b * TT + (tc) * 32           \
                                        + (idx >> 4)) * KK + (idx & 15) * 4];   \
        }                                                                       \
        _Pragma("unroll")                                                       \
        for (int i_ = 0; i_ < 4; i_++) {                                        \
            int idx = tid + i_ * 256;                                           \
            pX[i_] = *(const float4*)&x[(size_t)(b * TT + (tc) * 32             \
                                        + (idx >> 5)) * DD + dt * 128           \
                                        + (idx & 31) * 4];                      \
        }                                                                       \
    } while (0)
#define K2_STS()                                                                \
    do {                                                                        \
        _Pragma("unroll")                                                       \
        for (int i_ = 0; i_ < 2; i_++) {                                        \
            int idx = tid + i_ * 256;                                           \
            float4 h_, l_;                                                      \
            h_.x = tf32_rna(pA[i_].x); l_.x = pA[i_].x - h_.x;                  \
            h_.y = tf32_rna(pA[i_].y); l_.y = pA[i_].y - h_.y;                  \
            h_.z = tf32_rna(pA[i_].z); l_.z = pA[i_].z - h_.z;                  \
            h_.w = tf32_rna(pA[i_].w); l_.w = pA[i_].w - h_.w;                  \
            *(float4*)&sAh[(idx >> 4) * 72 + (idx & 15) * 4] = h_;              \
            *(float4*)&sAl[(idx >> 4) * 72 + (idx & 15) * 4] = l_;              \
        }                                                                       \
        _Pragma("unroll")                                                       \
        for (int i_ = 0; i_ < 4; i_++) {                                        \
            int idx = tid + i_ * 256;                                           \
            *(float4*)&sX2[(idx >> 5) * 136 + (idx & 31) * 4] = pX[i_];         \
        }                                                                       \
    } while (0)

    K2_LDG(0);
    K2_STS();
    __syncthreads();

    const int NC = 32;   // 32 chunks x 32 t = 1024 t
    for (int c = 0; c < NC; c++) {
        if (c + 1 < NC) K2_LDG(c + 1);

#pragma unroll
        for (int ks = 0; ks < 4; ks++) {
            const int k0 = ks * 8;
            unsigned ah[2][4], al[2][4];
#pragma unroll
            for (int mt = 0; mt < 2; mt++) {
                const int m0 = (mh2 + mt) * 16;
                ah[mt][0] = __float_as_uint(sAh[(k0 + qid) * 72 + m0 + grp]);
                ah[mt][1] = __float_as_uint(sAh[(k0 + qid) * 72 + m0 + grp + 8]);
                ah[mt][2] = __float_as_uint(sAh[(k0 + qid + 4) * 72 + m0 + grp]);
                ah[mt][3] = __float_as_uint(sAh[(k0 + qid + 4) * 72 + m0 + grp + 8]);
                al[mt][0] = __float_as_uint(sAl[(k0 + qid) * 72 + m0 + grp]);
                al[mt][1] = __float_as_uint(sAl[(k0 + qid) * 72 + m0 + grp + 8]);
                al[mt][2] = __float_as_uint(sAl[(k0 + qid + 4) * 72 + m0 + grp]);
                al[mt][3] = __float_as_uint(sAl[(k0 + qid + 4) * 72 + m0 + grp + 8]);
            }
#pragma unroll
            for (int j = 0; j < 4; j++) {
                const int n = nb + j * 8 + grp;
                float b0f = sX2[(k0 + qid) * 136 + n];
                float b1f = sX2[(k0 + qid + 4) * 136 + n];
                float bh0f = tf32_rna(b0f), bh1f = tf32_rna(b1f);
                unsigned bh0 = __float_as_uint(bh0f), bh1 = __float_as_uint(bh1f);
                unsigned bl0 = __float_as_uint(b0f - bh0f);
                unsigned bl1 = __float_as_uint(b1f - bh1f);
#pragma unroll
                for (int mt = 0; mt < 2; mt++) {
                    MMA8(C[mt][j], ah[mt][0], ah[mt][1], ah[mt][2], ah[mt][3], bh0, bh1);
                    MMA8(C[mt][j], ah[mt][0], ah[mt][1], ah[mt][2], ah[mt][3], bl0, bl1);
                    MMA8(C[mt][j], al[mt][0], al[mt][1], al[mt][2], al[mt][3], bh0, bh1);
                }
            }
        }
        __syncthreads();
        if (c + 1 < NC) {
            K2_STS();
            __syncthreads();
        }
    }
#undef K2_LDG
#undef K2_STS

#pragma unroll
    for (int mt = 0; mt < 2; mt++)
#pragma unroll
        for (int j = 0; j < 4; j++) {
            const int center = (mh2 + mt) * 16 + grp;
            const int d = dt * 128 + nb + j * 8 + qid * 2;
            *(float2*)&g_agg[((size_t)b * KK + center) * DD + d] =
                make_float2(C[mt][j][0], C[mt][j][1]);
            *(float2*)&g_agg[((size_t)b * KK + center + 8) * DD + d] =
                make_float2(C[mt][j][2], C[mt][j][3]);
        }
}

// K3: residual + intra-normalize; write tf32-hi / residual split rows of v
__global__ __launch_bounds__(128) void k_norm(const float* __restrict__ centers) {
    const int bx = blockIdx.x;
    const int b = bx >> 6;
    const int k = bx & 63;
    const int tid = threadIdx.x;

    const float sw = g_sumw[b * KK + k];
    const size_t base = ((size_t)b * KK + k) * DD;

    float4 xa = *(float4*)&g_agg[base + tid * 4];
    float4 c  = *(const float4*)&centers[(size_t)k * DD + tid * 4];
    float4 f;
    f.x = xa.x - sw * c.x; f.y = xa.y - sw * c.y;
    f.z = xa.z - sw * c.z; f.w = xa.w - sw * c.w;
    float ss = f.x * f.x + f.y * f.y + f.z * f.z + f.w * f.w;
#pragma unroll
    for (int off = 16; off > 0; off >>= 1)
        ss += __shfl_xor_sync(0xffffffffu, ss, off);

    __shared__ float wsum[4];
    __shared__ float scale_s;
    if ((tid & 31) == 0) wsum[tid >> 5] = ss;
    __syncthreads();
    if (tid == 0) {
        float tot = wsum[0] + wsum[1] + wsum[2] + wsum[3];
        float sc = rsqrtf(fmaxf(tot, F_EPS));
        scale_s = sc;
        atomicAdd(&g_norm2[b], tot * sc * sc);
    }
    __syncthreads();
    float sc = scale_s;
    float v0 = f.x * sc, v1 = f.y * sc, v2 = f.z * sc, v3 = f.w * sc;
    float h0 = tf32_rna(v0), h1 = tf32_rna(v1), h2 = tf32_rna(v2), h3 = tf32_rna(v3);
    size_t col = (size_t)k * DD + tid * 4;
    *(float4*)&g_v64[(size_t)b * KD + col] = make_float4(h0, h1, h2, h3);
    *(float4*)&g_v64[(size_t)(b + 32) * KD + col] =
        make_float4(v0 - h0, v1 - h1, v2 - h2, v3 - h3);
}

// ---------------------------------------------------------------------------
// K4 (R13 proven): out = v @ R. Depth-3 cp.async, 16-kd chunks, red.v2.
// ---------------------------------------------------------------------------
__global__ __launch_bounds__(128) void k_out_mma(const float* __restrict__ R,
                                                 float* __restrict__ out) {
    __shared__ __align__(16) float sV[3][64 * 20];
    __shared__ __align__(16) float sR[3][16 * 136];

    const int tid = threadIdx.x;
    const int lane = tid & 31, warp = tid >> 5;
    const int grp = lane >> 2, qid = lane & 3;
    const int mh = (warp & 1) * 16;
    const int nb = (warp >> 1) * 64;
    const int o0 = (blockIdx.x & 7) * 128;
    const int kd_base = (blockIdx.x >> 3) * 512;

    float C[8][4];
#pragma unroll
    for (int j = 0; j < 8; j++)
#pragma unroll
        for (int q = 0; q < 4; q++) C[j][q] = 0.0f;

    const float4* R4 = (const float4*)R;
    const float4* V4 = (const float4*)g_v64;

#define K4_CP(cc, p)                                                              \
    do {                                                                          \
        _Pragma("unroll")                                                         \
        for (int i_ = 0; i_ < 4; i_++) {                                          \
            int idx = tid + i_ * 128;                                             \
            int row = idx >> 5, col = idx & 31;                                   \
            cp16cg(&sR[p][row * 136 + col * 4],                                   \
                   &R4[(size_t)(kd_base + (cc) * 16 + row) * 256 + (o0 >> 2) + col]); \
        }                                                                         \
        _Pragma("unroll")                                                         \
        for (int i_ = 0; i_ < 2; i_++) {                                          \
            int idx = tid + i_ * 128;                                             \
            int row = idx >> 2, col = idx & 3;                                    \
            cp16ca(&sV[p][row * 20 + col * 4],                                    \
                   &V4[(size_t)row * (KD / 4) + ((kd_base + (cc) * 16) >> 2) + col]); \
        }                                                                         \
        CP_COMMIT();                                                              \
    } while (0)

    K4_CP(0, 0);
    K4_CP(1, 1);
    K4_CP(2, 2);

    const int NC = 32;
    for (int c = 0; c < NC; c++) {
        const int p = c % 3;
        if (c + 2 < NC) CP_WAIT2();
        else if (c + 1 < NC) CP_WAIT1();
        else CP_WAIT0();
        __syncthreads();

#pragma unroll
        for (int ks = 0; ks < 2; ks++) {
            const int k0 = ks * 8;
            unsigned ah[4], al[4];
            ah[0] = __float_as_uint(sV[p][(mh + grp) * 20 + k0 + qid]);
            ah[1] = __float_as_uint(sV[p][(mh + grp + 8) * 20 + k0 + qid]);
            ah[2] = __float_as_uint(sV[p][(mh + grp) * 20 + k0 + qid + 4]);
            ah[3] = __float_as_uint(sV[p][(mh + grp + 8) * 20 + k0 + qid + 4]);
            al[0] = __float_as_uint(sV[p][(32 + mh + grp) * 20 + k0 + qid]);
            al[1] = __float_as_uint(sV[p][(32 + mh + grp + 8) * 20 + k0 + qid]);
            al[2] = __float_as_uint(sV[p][(32 + mh + grp) * 20 + k0 + qid + 4]);
            al[3] = __float_as_uint(sV[p][(32 + mh + grp + 8) * 20 + k0 + qid + 4]);
#pragma unroll
            for (int j = 0; j < 8; j++) {
                const int n = nb + j * 8 + grp;
                unsigned b0 = __float_as_uint(sR[p][(k0 + qid) * 136 + n]);
                unsigned b1 = __float_as_uint(sR[p][(k0 + qid + 4) * 136 + n]);
                MMA8(C[j], ah[0], ah[1], ah[2], ah[3], b0, b1);
                MMA8(C[j], al[0], al[1], al[2], al[3], b0, b1);
            }
        }
        __syncthreads();
        if (c + 3 < NC) K4_CP(c + 3, p);
    }
#undef K4_CP

    const int row0 = mh + grp;
#pragma unroll
    for (int j = 0; j < 8; j++) {
        const int col = o0 + nb + j * 8 + qid * 2;
        red2(&out[(size_t)row0 * OO + col], C[j][0], C[j][1]);
        red2(&out[(size_t)(row0 + 8) * OO + col], C[j][2], C[j][3]);
    }
}

__global__ __launch_bounds__(256) void k_finish(float* __restrict__ out) {
    int i = blockIdx.x * 256 + threadIdx.x;
    int b = i >> 10;
    out[i] *= rsqrtf(fmaxf(g_norm2[b], F_EPS));
}

extern "C" void kernel_launch(void* const* d_in, const int* in_sizes, int n_in,
                              void* d_out, int out_size) {
    const float* x       = (const float*)d_in[0];
    const float* w       = (const float*)d_in[1];
    const float* bias    = (const float*)d_in[2];
    const float* centers = (const float*)d_in[3];
    const float* R       = (const float*)d_in[4];
    float* out = (float*)d_out;

    void *p_sumw, *p_norm2;
    cudaGetSymbolAddress(&p_sumw, g_sumw);
    cudaGetSymbolAddress(&p_norm2, g_norm2);

    cudaMemsetAsync(p_sumw, 0, sizeof(float) * BB * KK);
    cudaMemsetAsync(p_norm2, 0, sizeof(float) * BB);
    cudaMemsetAsync(d_out, 0, sizeof(float) * BB * OO);

    k_assign_mma<<<256, 256>>>(x, w, bias);
    k_agg_mma<<<128, 256>>>(x);
    k_norm<<<2048, 128>>>(centers);
    k_out_mma<<<512, 128>>>(R, out);
    k_finish<<<128, 256>>>(out);
}

// round 17
// speedup vs baseline: 1.1889x; 1.1889x over previous
#include <cuda_runtime.h>
#include <math.h>

#define BB 32
#define TT 1024
#define DD 512
#define KK 64
#define OO 1024
#define KD (KK * DD)
#define F_EPS 1e-12f

typedef unsigned long long ull;

__device__ __forceinline__ float tf32_rna(float v) {
    float h; asm("cvt.rna.tf32.f32 %0, %1;" : "=f"(h) : "f"(v)); return h;
}
__device__ __forceinline__ void red2(float* p, float a, float b) {
    asm volatile("red.global.add.v2.f32 [%0], {%1, %2};"
                 :: "l"(p), "f"(a), "f"(b) : "memory");
}
__device__ __forceinline__ void cp16cg(void* s, const void* g) {
    unsigned a = (unsigned)__cvta_generic_to_shared(s);
    asm volatile("cp.async.cg.shared.global [%0], [%1], 16;" :: "r"(a), "l"(g) : "memory");
}
__device__ __forceinline__ void cp16ca(void* s, const void* g) {
    unsigned a = (unsigned)__cvta_generic_to_shared(s);
    asm volatile("cp.async.ca.shared.global [%0], [%1], 16;" :: "r"(a), "l"(g) : "memory");
}
#define CP_COMMIT() asm volatile("cp.async.commit_group;" ::: "memory")
#define CP_WAIT2()  asm volatile("cp.async.wait_group 2;" ::: "memory")
#define CP_WAIT1()  asm volatile("cp.async.wait_group 1;" ::: "memory")
#define CP_WAIT0()  asm volatile("cp.async.wait_group 0;" ::: "memory")

#define MMA8(Cp, a0, a1, a2, a3, b0, b1)                                        \
    asm volatile(                                                               \
        "mma.sync.aligned.m16n8k8.row.col.f32.tf32.tf32.f32 "                   \
        "{%0,%1,%2,%3}, {%4,%5,%6,%7}, {%8,%9}, {%0,%1,%2,%3};"                 \
        : "+f"((Cp)[0]), "+f"((Cp)[1]), "+f"((Cp)[2]), "+f"((Cp)[3])            \
        : "r"(a0), "r"(a1), "r"(a2), "r"(a3), "r"(b0), "r"(b1))

__device__ float g_a[BB * TT * KK];
__device__ float g_agg[BB * KK * DD];
__device__ float g_v64[64 * KD];     // rows 0-31: tf32-hi(v); rows 32-63: residual
__device__ float g_sumw[BB * KK];
__device__ float g_norm2[BB];

// ---------------------------------------------------------------------------
// K1: logits -> softmax -> a, sum_w. 2-product split: x pre-split hi/lo at
// STS (A-side exact), W raw (HW tf32-truncates B once). 128 thr, R12 shape.
// ---------------------------------------------------------------------------
__global__ __launch_bounds__(128) void k_assign_mma(const float* __restrict__ x,
                                                    const float* __restrict__ w,
                                                    const float* __restrict__ bias) {
    __shared__ __align__(16) float sXh[128 * 36];   // [row][32 d] hi
    __shared__ __align__(16) float sXl[128 * 36];   // [row][32 d] lo
    __shared__ __align__(16) float sW[32 * 72];     // [d][64 k] raw
    __shared__ float bias_s[64];
    __shared__ float ssum[64];

    const int tid = threadIdx.x;
    const int lane = tid & 31, warp = tid >> 5;
    const int grp = lane >> 2, qid = lane & 3;
    const int r0 = blockIdx.x * 128;
    const int b = r0 >> 10;

    if (tid < 64) { ssum[tid] = 0.0f; bias_s[tid] = bias[tid]; }

    float C[2][8][4];
#pragma unroll
    for (int t = 0; t < 2; t++)
#pragma unroll
        for (int j = 0; j < 8; j++)
#pragma unroll
            for (int q = 0; q < 4; q++) C[t][j][q] = 0.0f;

    float4 pX[8], pW[4];

#define K1_LDG(c0)                                                              \
    do {                                                                        \
        _Pragma("unroll")                                                       \
        for (int i_ = 0; i_ < 8; i_++) {                                        \
            int idx = tid + i_ * 128;                                           \
            pX[i_] = *(const float4*)&x[(size_t)(r0 + (idx >> 3)) * DD + (c0)   \
                                        + (idx & 7) * 4];                       \
        }                                                                       \
        _Pragma("unroll")                                                       \
        for (int i_ = 0; i_ < 4; i_++) {                                        \
            int idx = tid + i_ * 128;                                           \
            pW[i_] = *(const float4*)&w[(size_t)((c0) + (idx >> 4)) * KK        \
                                        + (idx & 15) * 4];                      \
        }                                                                       \
    } while (0)
#define K1_STS()                                                                \
    do {                                                                        \
        _Pragma("unroll")                                                       \
        for (int i_ = 0; i_ < 8; i_++) {                                        \
            int idx = tid + i_ * 128;                                           \
            int off = (idx >> 3) * 36 + (idx & 7) * 4;                          \
            float4 h_, l_;                                                      \
            h_.x = tf32_rna(pX[i_].x); l_.x = pX[i_].x - h_.x;                  \
            h_.y = tf32_rna(pX[i_].y); l_.y = pX[i_].y - h_.y;                  \
            h_.z = tf32_rna(pX[i_].z); l_.z = pX[i_].z - h_.z;                  \
            h_.w = tf32_rna(pX[i_].w); l_.w = pX[i_].w - h_.w;                  \
            *(float4*)&sXh[off] = h_;                                           \
            *(float4*)&sXl[off] = l_;                                           \
        }                                                                       \
        _Pragma("unroll")                                                       \
        for (int i_ = 0; i_ < 4; i_++) {                                        \
            int idx = tid + i_ * 128;                                           \
            *(float4*)&sW[(idx >> 4) * 72 + (idx & 15) * 4] = pW[i_];           \
        }                                                                       \
    } while (0)

    K1_LDG(0);
    K1_STS();
    __syncthreads();

    const int NC = DD / 32;   // 16
    for (int c = 0; c < NC; c++) {
        if (c + 1 < NC) K1_LDG((c + 1) * 32);

#pragma unroll
        for (int ks = 0; ks < 4; ks++) {
            const int k0 = ks * 8;
            unsigned ah[2][4], al[2][4];
#pragma unroll
            for (int t = 0; t < 2; t++) {
                const int base = warp * 32 + t * 16;
                ah[t][0] = __float_as_uint(sXh[(base + grp) * 36 + k0 + qid]);
                ah[t][1] = __float_as_uint(sXh[(base + grp + 8) * 36 + k0 + qid]);
                ah[t][2] = __float_as_uint(sXh[(base + grp) * 36 + k0 + qid + 4]);
                ah[t][3] = __float_as_uint(sXh[(base + grp + 8) * 36 + k0 + qid + 4]);
                al[t][0] = __float_as_uint(sXl[(base + grp) * 36 + k0 + qid]);
                al[t][1] = __float_as_uint(sXl[(base + grp + 8) * 36 + k0 + qid]);
                al[t][2] = __float_as_uint(sXl[(base + grp) * 36 + k0 + qid + 4]);
                al[t][3] = __float_as_uint(sXl[(base + grp + 8) * 36 + k0 + qid + 4]);
            }
#pragma unroll
            for (int j = 0; j < 8; j++) {
                const int n = j * 8 + grp;
                unsigned b0 = __float_as_uint(sW[(k0 + qid) * 72 + n]);
                unsigned b1 = __float_as_uint(sW[(k0 + qid + 4) * 72 + n]);
#pragma unroll
                for (int t = 0; t < 2; t++) {
                    MMA8(C[t][j], ah[t][0], ah[t][1], ah[t][2], ah[t][3], b0, b1);
                    MMA8(C[t][j], al[t][0], al[t][1], al[t][2], al[t][3], b0, b1);
                }
            }
        }
        __syncthreads();
        if (c + 1 < NC) {
            K1_STS();
            __syncthreads();
        }
    }
#undef K1_LDG
#undef K1_STS

    float cs[8][2];
#pragma unroll
    for (int j = 0; j < 8; j++) { cs[j][0] = 0.0f; cs[j][1] = 0.0f; }

#pragma unroll
    for (int t = 0; t < 2; t++) {
#pragma unroll
        for (int s = 0; s < 2; s++) {
            float va[8], vb[8];
            float m = -1e30f;
#pragma unroll
            for (int j = 0; j < 8; j++) {
                va[j] = C[t][j][s * 2 + 0] + bias_s[j * 8 + qid * 2];
                vb[j] = C[t][j][s * 2 + 1] + bias_s[j * 8 + qid * 2 + 1];
                m = fmaxf(m, fmaxf(va[j], vb[j]));
            }
            m = fmaxf(m, __shfl_xor_sync(0xffffffffu, m, 1));
            m = fmaxf(m, __shfl_xor_sync(0xffffffffu, m, 2));
            float sm = 0.0f;
#pragma unroll
            for (int j = 0; j < 8; j++) {
                va[j] = __expf(va[j] - m);
                vb[j] = __expf(vb[j] - m);
                sm += va[j] + vb[j];
            }
            sm += __shfl_xor_sync(0xffffffffu, sm, 1);
            sm += __shfl_xor_sync(0xffffffffu, sm, 2);
            float inv = 1.0f / sm;
            const int row = r0 + warp * 32 + t * 16 + s * 8 + grp;
#pragma unroll
            for (int j = 0; j < 8; j++) {
                float2 o;
                o.x = va[j] * inv; o.y = vb[j] * inv;
                *(float2*)&g_a[(size_t)row * KK + j * 8 + qid * 2] = o;
                cs[j][0] += o.x; cs[j][1] += o.y;
            }
        }
    }
#pragma unroll
    for (int j = 0; j < 8; j++) {
#pragma unroll
        for (int off = 4; off < 32; off <<= 1) {
            cs[j][0] += __shfl_xor_sync(0xffffffffu, cs[j][0], off);
            cs[j][1] += __shfl_xor_sync(0xffffffffu, cs[j][1], off);
        }
    }
    if (grp == 0) {
#pragma unroll
        for (int j = 0; j < 8; j++) {
            atomicAdd(&ssum[j * 8 + qid * 2], cs[j][0]);
            atomicAdd(&ssum[j * 8 + qid * 2 + 1], cs[j][1]);
        }
    }
    __syncthreads();
    if (tid < 64) atomicAdd(&g_sumw[b * KK + tid], ssum[tid]);
}

// ---------------------------------------------------------------------------
// K2: x_agg = a^T x. 2-product: a pre-split hi/lo (A-side exact), x raw.
// R12 shape: grid 256 (b x dtile x tseg2), 128 thr, NC=16 chunks of 32t, red2.
// ---------------------------------------------------------------------------
__global__ __launch_bounds__(128) void k_agg_mma(const float* __restrict__ x) {
    __shared__ __align__(16) float sAh[32 * 72];
    __shared__ __align__(16) float sAl[32 * 72];
    __shared__ __align__(16) float sX2[32 * 136];

    const int tid = threadIdx.x;
    const int lane = tid & 31, warp = tid >> 5;
    const int grp = lane >> 2, qid = lane & 3;
    const int bx = blockIdx.x;
    const int b   = bx >> 3;
    const int dt  = (bx >> 1) & 3;
    const int seg = bx & 1;
    const int t0  = seg * 512;
    const int nb  = warp * 32;

    float C[4][4][4];
#pragma unroll
    for (int mt = 0; mt < 4; mt++)
#pragma unroll
        for (int j = 0; j < 4; j++)
#pragma unroll
            for (int q = 0; q < 4; q++) C[mt][j][q] = 0.0f;

    float4 pA[4], pX[8];

#define K2_LDG(tc)                                                              \
    do {                                                                        \
        _Pragma("unroll")                                                       \
        for (int i_ = 0; i_ < 4; i_++) {                                        \
            int idx = tid + i_ * 128;                                           \
            pA[i_] = *(const float4*)&g_a[(size_t)(b * TT + t0 + (tc) * 32      \
                                        + (idx >> 4)) * KK + (idx & 15) * 4];   \
        }                                                                       \
        _Pragma("unroll")                                                       \
        for (int i_ = 0; i_ < 8; i_++) {                                        \
            int idx = tid + i_ * 128;                                           \
            pX[i_] = *(const float4*)&x[(size_t)(b * TT + t0 + (tc) * 32        \
                                        + (idx >> 5)) * DD + dt * 128           \
                                        + (idx & 31) * 4];                      \
        }                                                                       \
    } while (0)
#define K2_STS()                                                                \
    do {                                                                        \
        _Pragma("unroll")                                                       \
        for (int i_ = 0; i_ < 4; i_++) {                                        \
            int idx = tid + i_ * 128;                                           \
            int off = (idx >> 4) * 72 + (idx & 15) * 4;                         \
            float4 h_, l_;                                                      \
            h_.x = tf32_rna(pA[i_].x); l_.x = pA[i_].x - h_.x;                  \
            h_.y = tf32_rna(pA[i_].y); l_.y = pA[i_].y - h_.y;                  \
            h_.z = tf32_rna(pA[i_].z); l_.z = pA[i_].z - h_.z;                  \
            h_.w = tf32_rna(pA[i_].w); l_.w = pA[i_].w - h_.w;                  \
            *(float4*)&sAh[off] = h_;                                           \
            *(float4*)&sAl[off] = l_;                                           \
        }                                                                       \
        _Pragma("unroll")                                                       \
        for (int i_ = 0; i_ < 8; i_++) {                                        \
            int idx = tid + i_ * 128;                                           \
            *(float4*)&sX2[(idx >> 5) * 136 + (idx & 31) * 4] = pX[i_];         \
        }                                                                       \
    } while (0)

    K2_LDG(0);
    K2_STS();
    __syncthreads();

    const int NC = 16;
    for (int c = 0; c < NC; c++) {
        if (c + 1 < NC) K2_LDG(c + 1);

#pragma unroll
        for (int ks = 0; ks < 4; ks++) {
            const int k0 = ks * 8;
            unsigned ah[4][4], al[4][4];
#pragma unroll
            for (int mt = 0; mt < 4; mt++) {
                const int m0 = mt * 16;
                ah[mt][0] = __float_as_uint(sAh[(k0 + qid) * 72 + m0 + grp]);
                ah[mt][1] = __float_as_uint(sAh[(k0 + qid) * 72 + m0 + grp + 8]);
                ah[mt][2] = __float_as_uint(sAh[(k0 + qid + 4) * 72 + m0 + grp]);
                ah[mt][3] = __float_as_uint(sAh[(k0 + qid + 4) * 72 + m0 + grp + 8]);
                al[mt][0] = __float_as_uint(sAl[(k0 + qid) * 72 + m0 + grp]);
                al[mt][1] = __float_as_uint(sAl[(k0 + qid) * 72 + m0 + grp + 8]);
                al[mt][2] = __float_as_uint(sAl[(k0 + qid + 4) * 72 + m0 + grp]);
                al[mt][3] = __float_as_uint(sAl[(k0 + qid + 4) * 72 + m0 + grp + 8]);
            }
#pragma unroll
            for (int j = 0; j < 4; j++) {
                const int n = nb + j * 8 + grp;
                unsigned b0 = __float_as_uint(sX2[(k0 + qid) * 136 + n]);
                unsigned b1 = __float_as_uint(sX2[(k0 + qid + 4) * 136 + n]);
#pragma unroll
                for (int mt = 0; mt < 4; mt++) {
                    MMA8(C[mt][j], ah[mt][0], ah[mt][1], ah[mt][2], ah[mt][3], b0, b1);
                    MMA8(C[mt][j], al[mt][0], al[mt][1], al[mt][2], al[mt][3], b0, b1);
                }
            }
        }
        __syncthreads();
        if (c + 1 < NC) {
            K2_STS();
            __syncthreads();
        }
    }
#undef K2_LDG
#undef K2_STS

#pragma unroll
    for (int mt = 0; mt < 4; mt++)
#pragma unroll
        for (int j = 0; j < 4; j++) {
            const int center = mt * 16 + grp;
            const int d = dt * 128 + nb + j * 8 + qid * 2;
            red2(&g_agg[((size_t)b * KK + center) * DD + d], C[mt][j][0], C[mt][j][1]);
            red2(&g_agg[((size_t)b * KK + center + 8) * DD + d], C[mt][j][2], C[mt][j][3]);
        }
}

// K3: residual + intra-normalize; write tf32-hi / residual split rows of v
__global__ __launch_bounds__(128) void k_norm(const float* __restrict__ centers) {
    const int bx = blockIdx.x;
    const int b = bx >> 6;
    const int k = bx & 63;
    const int tid = threadIdx.x;

    const float sw = g_sumw[b * KK + k];
    const size_t base = ((size_t)b * KK + k) * DD;

    float4 xa = *(float4*)&g_agg[base + tid * 4];
    float4 c  = *(const float4*)&centers[(size_t)k * DD + tid * 4];
    float4 f;
    f.x = xa.x - sw * c.x; f.y = xa.y - sw * c.y;
    f.z = xa.z - sw * c.z; f.w = xa.w - sw * c.w;
    float ss = f.x * f.x + f.y * f.y + f.z * f.z + f.w * f.w;
#pragma unroll
    for (int off = 16; off > 0; off >>= 1)
        ss += __shfl_xor_sync(0xffffffffu, ss, off);

    __shared__ float wsum[4];
    __shared__ float scale_s;
    if ((tid & 31) == 0) wsum[tid >> 5] = ss;
    __syncthreads();
    if (tid == 0) {
        float tot = wsum[0] + wsum[1] + wsum[2] + wsum[3];
        float sc = rsqrtf(fmaxf(tot, F_EPS));
        scale_s = sc;
        atomicAdd(&g_norm2[b], tot * sc * sc);
    }
    __syncthreads();
    float sc = scale_s;
    float v0 = f.x * sc, v1 = f.y * sc, v2 = f.z * sc, v3 = f.w * sc;
    float h0 = tf32_rna(v0), h1 = tf32_rna(v1), h2 = tf32_rna(v2), h3 = tf32_rna(v3);
    size_t col = (size_t)k * DD + tid * 4;
    *(float4*)&g_v64[(size_t)b * KD + col] = make_float4(h0, h1, h2, h3);
    *(float4*)&g_v64[(size_t)(b + 32) * KD + col] =
        make_float4(v0 - h0, v1 - h1, v2 - h2, v3 - h3);
}

// ---------------------------------------------------------------------------
// K4 (R13 proven): out = v @ R. Depth-3 cp.async, 16-kd chunks, red.v2.
// ---------------------------------------------------------------------------
__global__ __launch_bounds__(128) void k_out_mma(const float* __restrict__ R,
                                                 float* __restrict__ out) {
    __shared__ __align__(16) float sV[3][64 * 20];
    __shared__ __align__(16) float sR[3][16 * 136];

    const int tid = threadIdx.x;
    const int lane = tid & 31, warp = tid >> 5;
    const int grp = lane >> 2, qid = lane & 3;
    const int mh = (warp & 1) * 16;
    const int nb = (warp >> 1) * 64;
    const int o0 = (blockIdx.x & 7) * 128;
    const int kd_base = (blockIdx.x >> 3) * 512;

    float C[8][4];
#pragma unroll
    for (int j = 0; j < 8; j++)
#pragma unroll
        for (int q = 0; q < 4; q++) C[j][q] = 0.0f;

    const float4* R4 = (const float4*)R;
    const float4* V4 = (const float4*)g_v64;

#define K4_CP(cc, p)                                                              \
    do {                                                                          \
        _Pragma("unroll")                                                         \
        for (int i_ = 0; i_ < 4; i_++) {                                          \
            int idx = tid + i_ * 128;                                             \
            int row = idx >> 5, col = idx & 31;                                   \
            cp16cg(&sR[p][row * 136 + col * 4],                                   \
                   &R4[(size_t)(kd_base + (cc) * 16 + row) * 256 + (o0 >> 2) + col]); \
        }                                                                         \
        _Pragma("unroll")                                                         \
        for (int i_ = 0; i_ < 2; i_++) {                                          \
            int idx = tid + i_ * 128;                                             \
            int row = idx >> 2, col = idx & 3;                                    \
            cp16ca(&sV[p][row * 20 + col * 4],                                    \
                   &V4[(size_t)row * (KD / 4) + ((kd_base + (cc) * 16) >> 2) + col]); \
        }                                                                         \
        CP_COMMIT();                                                              \
    } while (0)

    K4_CP(0, 0);
    K4_CP(1, 1);
    K4_CP(2, 2);

    const int NC = 32;
    for (int c = 0; c < NC; c++) {
        const int p = c % 3;
        if (c + 2 < NC) CP_WAIT2();
        else if (c + 1 < NC) CP_WAIT1();
        else CP_WAIT0();
        __syncthreads();

#pragma unroll
        for (int ks = 0; ks < 2; ks++) {
            const int k0 = ks * 8;
            unsigned ah[4], al[4];
            ah[0] = __float_as_uint(sV[p][(mh + grp) * 20 + k0 + qid]);
            ah[1] = __float_as_uint(sV[p][(mh + grp + 8) * 20 + k0 + qid]);
            ah[2] = __float_as_uint(sV[p][(mh + grp) * 20 + k0 + qid + 4]);
            ah[3] = __float_as_uint(sV[p][(mh + grp + 8) * 20 + k0 + qid + 4]);
            al[0] = __float_as_uint(sV[p][(32 + mh + grp) * 20 + k0 + qid]);
            al[1] = __float_as_uint(sV[p][(32 + mh + grp + 8) * 20 + k0 + qid]);
            al[2] = __float_as_uint(sV[p][(32 + mh + grp) * 20 + k0 + qid + 4]);
            al[3] = __float_as_uint(sV[p][(32 + mh + grp + 8) * 20 + k0 + qid + 4]);
#pragma unroll
            for (int j = 0; j < 8; j++) {
                const int n = nb + j * 8 + grp;
                unsigned b0 = __float_as_uint(sR[p][(k0 + qid) * 136 + n]);
                unsigned b1 = __float_as_uint(sR[p][(k0 + qid + 4) * 136 + n]);
                MMA8(C[j], ah[0], ah[1], ah[2], ah[3], b0, b1);
                MMA8(C[j], al[0], al[1], al[2], al[3], b0, b1);
            }
        }
        __syncthreads();
        if (c + 3 < NC) K4_CP(c + 3, p);
    }
#undef K4_CP

    const int row0 = mh + grp;
#pragma unroll
    for (int j = 0; j < 8; j++) {
        const int col = o0 + nb + j * 8 + qid * 2;
        red2(&out[(size_t)row0 * OO + col], C[j][0], C[j][1]);
        red2(&out[(size_t)(row0 + 8) * OO + col], C[j][2], C[j][3]);
    }
}

__global__ __launch_bounds__(256) void k_finish(float* __restrict__ out) {
    int i = blockIdx.x * 256 + threadIdx.x;
    int b = i >> 10;
    out[i] *= rsqrtf(fmaxf(g_norm2[b], F_EPS));
}

extern "C" void kernel_launch(void* const* d_in, const int* in_sizes, int n_in,
                              void* d_out, int out_size) {
    const float* x       = (const float*)d_in[0];
    const float* w       = (const float*)d_in[1];
    const float* bias    = (const float*)d_in[2];
    const float* centers = (const float*)d_in[3];
    const float* R       = (const float*)d_in[4];
    float* out = (float*)d_out;

    void *p_agg, *p_sumw, *p_norm2;
    cudaGetSymbolAddress(&p_agg, g_agg);
    cudaGetSymbolAddress(&p_sumw, g_sumw);
    cudaGetSymbolAddress(&p_norm2, g_norm2);

    cudaMemsetAsync(p_agg, 0, sizeof(float) * BB * KK * DD);
    cudaMemsetAsync(p_sumw, 0, sizeof(float) * BB * KK);
    cudaMemsetAsync(p_norm2, 0, sizeof(float) * BB);
    cudaMemsetAsync(d_out, 0, sizeof(float) * BB * OO);

    k_assign_mma<<<256, 128>>>(x, w, bias);
    k_agg_mma<<<256, 128>>>(x);
    k_norm<<<2048, 128>>>(centers);
    k_out_mma<<<512, 128>>>(R, out);
    k_finish<<<128, 256>>>(out);
}